// round 14
// baseline (speedup 1.0000x reference)
#include <cuda_runtime.h>
#include <cuda_bf16.h>
#include <cuda_fp16.h>
#include <math.h>
#include <stdint.h>

// Problem constants
#define BATCH 2
#define SEQ   2048
#define DMODEL 1024
#define NHEAD 16
#define DHEAD 64
#define MROWS (BATCH * SEQ)           // 4096
#define QKV_COLS (3 * DMODEL)         // 3072
#define QSCALE 0.18033688f            // 0.125 * log2(e)

// ---------------------------------------------------------------------------
// Scratch (static device globals; allocations are forbidden)
// ---------------------------------------------------------------------------
__device__ __half g_aP[(size_t)MROWS * DMODEL];            // 8.4 MB (A fp16, both GEMMs)
__device__ __half g_w1P[(size_t)QKV_COLS * DMODEL];        // 6.3 MB (W_qkv^T fp16)
__device__ __half g_w2P[(size_t)DMODEL * DMODEL];          // 2.1 MB (W_o^T fp16)
// Attention operands (plain fp16, all [b,h,t,64])
__device__ __half g_qp[(size_t)BATCH * NHEAD * SEQ * DHEAD];  // 8.4 MB
__device__ __half g_kp[(size_t)BATCH * NHEAD * SEQ * DHEAD];  // 8.4 MB
__device__ __half g_vp[(size_t)BATCH * NHEAD * SEQ * DHEAD];  // 8.4 MB

__device__ __forceinline__ uint32_t smem_u32(const void* p) {
    uint32_t a;
    asm("{ .reg .u64 t; cvta.to.shared.u64 t, %1; cvt.u32.u64 %0, t; }" : "=r"(a) : "l"(p));
    return a;
}
__device__ __forceinline__ float fast_exp2(float x) {
    float y; asm("ex2.approx.ftz.f32 %0, %1;" : "=f"(y) : "f"(x)); return y;
}
// pack fp16x2: low half = lo, high half = hi
__device__ __forceinline__ uint32_t pack_f16x2(float lo, float hi) {
    uint32_t r; asm("cvt.rn.f16x2.f32 %0, %1, %2;" : "=r"(r) : "f"(hi), "f"(lo)); return r;
}

#define LDMATRIX_X4(r0, r1, r2, r3, addr) \
    asm volatile("ldmatrix.sync.aligned.m8n8.x4.shared.b16 {%0,%1,%2,%3}, [%4];" \
        : "=r"(r0), "=r"(r1), "=r"(r2), "=r"(r3) : "r"(addr))

#define LDMATRIX_X4_TRANS(r0, r1, r2, r3, addr) \
    asm volatile("ldmatrix.sync.aligned.m8n8.x4.trans.shared.b16 {%0,%1,%2,%3}, [%4];" \
        : "=r"(r0), "=r"(r1), "=r"(r2), "=r"(r3) : "r"(addr))

#define MMA_F16(acc, a0, a1, a2, a3, b0, b1) \
    asm volatile( \
        "mma.sync.aligned.m16n8k16.row.col.f32.f16.f16.f32 " \
        "{%0,%1,%2,%3}, {%4,%5,%6,%7}, {%8,%9}, {%0,%1,%2,%3};" \
        : "+f"((acc)[0]), "+f"((acc)[1]), "+f"((acc)[2]), "+f"((acc)[3]) \
        : "r"(a0), "r"(a1), "r"(a2), "r"(a3), "r"(b0), "r"(b1))

// ---------------------------------------------------------------------------
// Merged conversion kernel (single launch):
//   section 0: x fp32 -> aP fp16                  (4096 blocks)
//   section 1: W_qkv -> w1P transpose-cast        (3072 blocks)
//   section 2: W_o   -> w2P transpose-cast        (1024 blocks)
// ---------------------------------------------------------------------------
__global__ void __launch_bounds__(256) conv_all_kernel(
    const float* __restrict__ x, const float* __restrict__ Wq,
    const float* __restrict__ Wo,
    __half* __restrict__ aP, __half* __restrict__ w1P, __half* __restrict__ w2P)
{
    const int bid = blockIdx.x;
    const int tid = threadIdx.x;

    if (bid < 4096) {
        size_t j = (size_t)bid * 256 + tid;
        float4 v = *(const float4*)(x + 4 * j);
        __half2* o = (__half2*)(aP + 4 * j);
        o[0] = __half2(__float2half_rn(v.x), __float2half_rn(v.y));
        o[1] = __half2(__float2half_rn(v.z), __float2half_rn(v.w));
        return;
    }

    __shared__ float t[32][33];
    const int tx = tid & 31, ty = tid >> 5;
    const float* W;
    __half* out;
    int N, bx, by;
    if (bid < 4096 + 3072) {
        int idx = bid - 4096;
        W = Wq; out = w1P; N = QKV_COLS;
        bx = idx % (QKV_COLS / 32); by = idx / (QKV_COLS / 32);
    } else {
        int idx = bid - 4096 - 3072;
        W = Wo; out = w2P; N = DMODEL;
        bx = idx % (DMODEL / 32); by = idx / (DMODEL / 32);
    }
#pragma unroll
    for (int i = 0; i < 4; i++) {
        int k = by * 32 + ty + 8 * i;
        int n = bx * 32 + tx;
        t[ty + 8 * i][tx] = W[(size_t)k * N + n];
    }
    __syncthreads();
#pragma unroll
    for (int i = 0; i < 4; i++) {
        int nl = ty + 8 * i;
        int n = bx * 32 + nl;
        out[(size_t)n * DMODEL + by * 32 + tx] = __float2half_rn(t[tx][nl]);
    }
}

// ---------------------------------------------------------------------------
// Shared GEMM fragment-compute body (per BK=32 sub-step of 2 k16 chunks,
// or BK=64 sub-step of 4 k16 chunks) -- inlined in the two loop macros.
// ---------------------------------------------------------------------------
#define GEMM_COMPUTE_STEP(sA, sB, ROWB_, ks)                                   \
    {                                                                          \
        uint32_t af[4][4];                                                     \
        _Pragma("unroll")                                                      \
        for (int mi = 0; mi < 4; mi++) {                                       \
            uint32_t addr = (sA) + (wm0 + mi * 16 + a_row_off) * (ROWB_) +     \
                            ((ks) * 2 + a_kch) * 16;                           \
            LDMATRIX_X4(af[mi][0], af[mi][1], af[mi][2], af[mi][3], addr);     \
        }                                                                      \
        uint32_t bfr[4][4];                                                    \
        _Pragma("unroll")                                                      \
        for (int nj = 0; nj < 4; nj++) {                                       \
            uint32_t addr = (sB) + (wn0 + nj * 16 + b_row_off) * (ROWB_) +     \
                            ((ks) * 2 + b_kch) * 16;                           \
            LDMATRIX_X4(bfr[nj][0], bfr[nj][1], bfr[nj][2], bfr[nj][3], addr); \
        }                                                                      \
        _Pragma("unroll")                                                      \
        for (int mi = 0; mi < 4; mi++)                                         \
            _Pragma("unroll")                                                  \
            for (int ni = 0; ni < 8; ni++)                                     \
                MMA_F16(acc[mi][ni], af[mi][0], af[mi][1], af[mi][2], af[mi][3], \
                        bfr[ni >> 1][(ni & 1) * 2 + 0], bfr[ni >> 1][(ni & 1) * 2 + 1]); \
    }

#define GEMM_COMMON_DECLS()                                                    \
    const int tid = threadIdx.x;                                               \
    const int warp = tid >> 5;                                                 \
    const int lane = tid & 31;                                                 \
    const int bm = blockIdx.y * 128;                                           \
    const int bn = blockIdx.x * 128;                                           \
    const int wm0 = (warp >> 1) * 64;                                          \
    const int wn0 = (warp & 1) * 64;                                           \
    const int a_row_off = (lane & 7) + ((lane >> 3) & 1) * 8;                  \
    const int a_kch = (lane >> 4);                                             \
    const int b_row_off = (lane & 7) + ((lane >> 4) & 1) * 8;                  \
    const int b_kch = (lane >> 3) & 1;                                         \
    const uint32_t sbase = smem_u32(gsm);                                      \
    float acc[4][8][4];                                                        \
    _Pragma("unroll")                                                          \
    for (int mi = 0; mi < 4; mi++)                                             \
        _Pragma("unroll")                                                      \
        for (int ni = 0; ni < 8; ni++)                                         \
            _Pragma("unroll")                                                  \
            for (int r = 0; r < 4; r++) acc[mi][ni][r] = 0.f;

// ---- BK=32, 5-stage pipeline (for the long-K QKV GEMM) ----
#define GBK1 32
#define ROWB1 80
#define STILE1 (128 * ROWB1)         // 10240 B
#define GSTAGE1 (2 * STILE1)         // 20480 B
#define NSTAGE1 5
#define GSMEM1 (NSTAGE1 * GSTAGE1)   // 102400 B

#define GEMM_LOOP_BK32()                                                       \
    GEMM_COMMON_DECLS()                                                        \
    const int NIT = K / GBK1;                                                  \
    auto load_stage = [&](int st, int k0) {                                    \
        uint32_t base = sbase + st * GSTAGE1;                                  \
        _Pragma("unroll")                                                      \
        for (int i = 0; i < 4; i++) {                                          \
            int c = tid + i * 128;               /* 0..511 */                  \
            int row = c >> 2, ch = c & 3;                                      \
            uint32_t dA = base + row * ROWB1 + ch * 16;                        \
            uint32_t dB = dA + STILE1;                                         \
            const __half* pA = A + (size_t)(bm + row) * K + k0 + ch * 8;       \
            const __half* pB = B + (size_t)(bn + row) * K + k0 + ch * 8;       \
            asm volatile("cp.async.cg.shared.global [%0], [%1], 16;\n" :: "r"(dA), "l"(pA) : "memory"); \
            asm volatile("cp.async.cg.shared.global [%0], [%1], 16;\n" :: "r"(dB), "l"(pB) : "memory"); \
        }                                                                      \
    };                                                                         \
    _Pragma("unroll")                                                          \
    for (int p = 0; p < NSTAGE1 - 1; p++) {                                    \
        load_stage(p, p * GBK1);                                               \
        asm volatile("cp.async.commit_group;\n" ::: "memory");                 \
    }                                                                          \
    int st = 0;                                                                \
    for (int it = 0; it < NIT; it++) {                                         \
        asm volatile("cp.async.wait_group %0;\n" :: "n"(NSTAGE1 - 2) : "memory"); \
        __syncthreads();                                                       \
        if (it + NSTAGE1 - 1 < NIT) {                                          \
            int st2 = st + NSTAGE1 - 1;                                        \
            if (st2 >= NSTAGE1) st2 -= NSTAGE1;                                \
            load_stage(st2, (it + NSTAGE1 - 1) * GBK1);                        \
        }                                                                      \
        asm volatile("cp.async.commit_group;\n" ::: "memory");                 \
        uint32_t sA = sbase + st * GSTAGE1;                                    \
        uint32_t sB = sA + STILE1;                                             \
        _Pragma("unroll")                                                      \
        for (int ks = 0; ks < 2; ks++) GEMM_COMPUTE_STEP(sA, sB, ROWB1, ks)    \
        st = (st + 1 == NSTAGE1) ? 0 : st + 1;                                 \
    }

// ---- BK=64, 3-stage pipeline (for the short-K out-projection) ----
#define GBK2 64
#define ROWB2 144
#define STILE2 (128 * ROWB2)         // 18432 B
#define GSTAGE2 (2 * STILE2)         // 36864 B
#define GSMEM2 (3 * GSTAGE2)         // 110592 B

#define GEMM_LOOP_BK64()                                                       \
    GEMM_COMMON_DECLS()                                                        \
    const int NIT = K / GBK2;                                                  \
    auto load_stage = [&](int st, int k0) {                                    \
        uint32_t base = sbase + st * GSTAGE2;                                  \
        _Pragma("unroll")                                                      \
        for (int i = 0; i < 8; i++) {                                          \
            int c = tid + i * 128;               /* 0..1023 */                 \
            int row = c >> 3, ch = c & 7;                                      \
            uint32_t dA = base + row * ROWB2 + ch * 16;                        \
            uint32_t dB = dA + STILE2;                                         \
            const __half* pA = A + (size_t)(bm + row) * K + k0 + ch * 8;       \
            const __half* pB = B + (size_t)(bn + row) * K + k0 + ch * 8;       \
            asm volatile("cp.async.cg.shared.global [%0], [%1], 16;\n" :: "r"(dA), "l"(pA) : "memory"); \
            asm volatile("cp.async.cg.shared.global [%0], [%1], 16;\n" :: "r"(dB), "l"(pB) : "memory"); \
        }                                                                      \
    };                                                                         \
    load_stage(0, 0);                                                          \
    asm volatile("cp.async.commit_group;\n" ::: "memory");                     \
    load_stage(1, GBK2);                                                       \
    asm volatile("cp.async.commit_group;\n" ::: "memory");                     \
    int st = 0;                                                                \
    for (int it = 0; it < NIT; it++) {                                         \
        asm volatile("cp.async.wait_group 1;\n" ::: "memory");                 \
        __syncthreads();                                                       \
        if (it + 2 < NIT) {                                                    \
            int st2 = st + 2 >= 3 ? st - 1 : st + 2;                           \
            load_stage(st2, (it + 2) * GBK2);                                  \
        }                                                                      \
        asm volatile("cp.async.commit_group;\n" ::: "memory");                 \
        uint32_t sA = sbase + st * GSTAGE2;                                    \
        uint32_t sB = sA + STILE2;                                             \
        _Pragma("unroll")                                                      \
        for (int ks = 0; ks < 4; ks++) GEMM_COMPUTE_STEP(sA, sB, ROWB2, ks)    \
        st = (st + 1 == 3) ? 0 : st + 1;                                       \
    }

// ---------------------------------------------------------------------------
// GEMM #2 (out-projection): BK=64/3-stage, plain fp32 epilogue.
// ---------------------------------------------------------------------------
__global__ void __launch_bounds__(128, 2) mma_gemm_kernel(
    const __half* __restrict__ A, const __half* __restrict__ B,
    float* __restrict__ C, int N, int K)
{
    extern __shared__ char gsm[];
    GEMM_LOOP_BK64()

    const int gr = lane >> 2;
    const int tc = (lane & 3) * 2;
#pragma unroll
    for (int mi = 0; mi < 4; mi++) {
#pragma unroll
        for (int ni = 0; ni < 8; ni++) {
            size_t r0 = (size_t)(bm + wm0 + mi * 16 + gr);
            int col = bn + wn0 + ni * 8 + tc;
            *(float2*)&C[r0 * N + col] = make_float2(acc[mi][ni][0], acc[mi][ni][1]);
            *(float2*)&C[(r0 + 8) * N + col] = make_float2(acc[mi][ni][2], acc[mi][ni][3]);
        }
    }
}

// ---------------------------------------------------------------------------
// GEMM #1 (QKV): BK=32/5-stage, fused epilogue writes fp16 Q (scaled)/K/V.
// bn in [0,1024) -> Q, [1024,2048) -> K, [2048,3072) -> V.
// ---------------------------------------------------------------------------
__global__ void __launch_bounds__(128, 2) mma_gemm_qkv_kernel(
    const __half* __restrict__ A, const __half* __restrict__ B,
    __half* __restrict__ qp, __half* __restrict__ kp,
    __half* __restrict__ vp, int N, int K)
{
    extern __shared__ char gsm[];
    GEMM_LOOP_BK32()

    const int gr = lane >> 2;
    const int tc = (lane & 3) * 2;
    const int sec = bn >> 10;                 // 0=Q, 1=K, 2=V
    const int colbase = (bn & 1023) + wn0;
    __half* const dst = (sec == 0) ? qp : ((sec == 1) ? kp : vp);

#pragma unroll
    for (int mi = 0; mi < 4; mi++) {
#pragma unroll
        for (int rr = 0; rr < 2; rr++) {
            const int row = bm + wm0 + mi * 16 + gr + rr * 8;
            const int b = row >> 11;
            const int t = row & (SEQ - 1);
#pragma unroll
            for (int ni = 0; ni < 8; ni++) {
                const int col = colbase + ni * 8 + tc;    // within section
                float v0 = acc[mi][ni][rr * 2 + 0];
                float v1 = acc[mi][ni][rr * 2 + 1];
                if (sec == 0) { v0 *= QSCALE; v1 *= QSCALE; }
                const int h = col >> 6;
                const int d = col & 63;
                size_t base = ((size_t)((b * NHEAD + h) * SEQ + t)) * DHEAD + d;
                *(__half2*)(dst + base) =
                    __half2(__float2half_rn(v0), __float2half_rn(v1));
            }
        }
    }
}

// ---------------------------------------------------------------------------
// Tensor-core flash attention (FA2), causal, plain fp16.
// CTA: 128 queries x 1 head; 8 warps (each m16 x 64-key tile), 256 threads.
// Q has its own smem region; prologue overlaps Q + K/V tile 0 + tile 1 loads.
// Fully-masked diagonal warps skip compute (bit-identical; their P was 0).
// ---------------------------------------------------------------------------
#define KPITCH 144                  // 64 fp16 = 128B data + 16 pad
#define KS_BYTES (64 * KPITCH)      // 9216
#define FSTAGE (2 * KS_BYTES)       // 18432 (K + V)
#define QS_BYTES (128 * KPITCH)     // 18432 (Q region)
#define FSMEM (2 * FSTAGE + QS_BYTES)  // 55296

__global__ void __launch_bounds__(256, 2) flash_mma_kernel(
    const __half* __restrict__ qp, const __half* __restrict__ kp,
    const __half* __restrict__ vp,
    __half* __restrict__ aP)
{
    extern __shared__ char fsm[];
    const int tid = threadIdx.x;
    const int warp = tid >> 5;
    const int lane = tid & 31;
    const int qt = gridDim.x - 1 - blockIdx.x;      // heavy tiles first
    const int h = blockIdx.y;
    const int b = blockIdx.z;
    const int bh = b * NHEAD + h;
    const int q0 = qt * 128;

    const uint32_t sb = smem_u32(fsm);
    const uint32_t qb = sb + 2 * FSTAGE;            // Q region
    const int gr = lane >> 2;
    const int tc = lane & 3;
    const int a_row_off = (lane & 7) + ((lane >> 3) & 1) * 8;
    const int a_kch = lane >> 4;
    const int b_row_off = (lane & 7) + ((lane >> 4) & 1) * 8;
    const int b_kch = (lane >> 3) & 1;
    // trans-ldmatrix addressing for V (row-major [key][d] tile)
    const int v_row_off = lane & 15;            // key within k16 chunk
    const int v_coff = (lane >> 4) * 16;        // d-half byte offset

    const int nkt = 2 * qt + 2;                 // k-tiles (64 keys each)

    auto load_tile = [&](int kt, int st) {
        const int kt0 = kt * 64;
        uint32_t ks = sb + st * FSTAGE;
        uint32_t vs = ks + KS_BYTES;
        const __half* ksrc = kp + ((size_t)(bh * SEQ + kt0)) * DHEAD;
        const __half* vsrc = vp + ((size_t)(bh * SEQ + kt0)) * DHEAD;
#pragma unroll
        for (int i = 0; i < 2; i++) {
            int c = i * 256 + tid;               // 0..511
            int row = c >> 3, ch = c & 7;
            uint32_t dk = ks + row * KPITCH + ch * 16;
            uint32_t dv = vs + row * KPITCH + ch * 16;
            const __half* sk = ksrc + (size_t)row * DHEAD + ch * 8;
            const __half* sv = vsrc + (size_t)row * DHEAD + ch * 8;
            asm volatile("cp.async.cg.shared.global [%0], [%1], 16;\n" :: "r"(dk), "l"(sk) : "memory");
            asm volatile("cp.async.cg.shared.global [%0], [%1], 16;\n" :: "r"(dv), "l"(sv) : "memory");
        }
    };

    // ---- overlapped prologue: Q + K/V tile 0 + K/V tile 1, then one wait
    {
        const __half* qsrc = qp + ((size_t)(bh * SEQ + q0)) * DHEAD;
#pragma unroll
        for (int i = 0; i < 4; i++) {
            int c = i * 256 + tid;               // 0..1023 (16B chunks)
            int row = c >> 3, ch = c & 7;
            uint32_t dst = qb + row * KPITCH + ch * 16;
            const __half* src = qsrc + (size_t)row * DHEAD + ch * 8;
            asm volatile("cp.async.cg.shared.global [%0], [%1], 16;\n" :: "r"(dst), "l"(src) : "memory");
        }
        asm volatile("cp.async.commit_group;\n" ::: "memory");
    }
    load_tile(0, 0);
    asm volatile("cp.async.commit_group;\n" ::: "memory");
    load_tile(1, 1);
    asm volatile("cp.async.commit_group;\n" ::: "memory");

    // Q group done when <=2 groups pending
    asm volatile("cp.async.wait_group 2;\n" ::: "memory");
    __syncthreads();

    uint32_t qf[4][4];
#pragma unroll
    for (int ck = 0; ck < 4; ck++) {
        uint32_t addr = qb + (warp * 16 + a_row_off) * KPITCH + ck * 32 + a_kch * 16;
        LDMATRIX_X4(qf[ck][0], qf[ck][1], qf[ck][2], qf[ck][3], addr);
    }

    float oacc[8][4];
#pragma unroll
    for (int t = 0; t < 8; t++)
#pragma unroll
        for (int r = 0; r < 4; r++) oacc[t][r] = 0.f;
    float m0 = -1e30f, m1 = -1e30f, l0 = 0.f, l1 = 0.f;

    for (int kt = 0; kt < nkt; kt++) {
        asm volatile("cp.async.wait_group 1;\n" ::: "memory");
        __syncthreads();
        const int st = kt & 1;
        uint32_t ks = sb + st * FSTAGE;
        uint32_t vs = ks + KS_BYTES;

        // warps 0-3 on the last k-tile are fully above the diagonal:
        // their P is exactly 0 there, so skip the compute entirely.
        const bool active = !(kt == nkt - 1 && warp < 4);
        if (active) {
            // ---- S = Q.K^T  (4 k16 chunks over DHEAD=64)
            float sacc[8][4];
#pragma unroll
            for (int t = 0; t < 8; t++)
#pragma unroll
                for (int r = 0; r < 4; r++) sacc[t][r] = 0.f;
#pragma unroll
            for (int ck = 0; ck < 4; ck++) {
                uint32_t bfr[4][4];
#pragma unroll
                for (int nj = 0; nj < 4; nj++) {
                    uint32_t addr = ks + (nj * 16 + b_row_off) * KPITCH + ck * 32 + b_kch * 16;
                    LDMATRIX_X4(bfr[nj][0], bfr[nj][1], bfr[nj][2], bfr[nj][3], addr);
                }
#pragma unroll
                for (int ni = 0; ni < 8; ni++)
                    MMA_F16(sacc[ni], qf[ck][0], qf[ck][1], qf[ck][2], qf[ck][3],
                            bfr[ni >> 1][(ni & 1) * 2 + 0], bfr[ni >> 1][(ni & 1) * 2 + 1]);
            }

            // ---- causal mask on the two diagonal-spanning k-tiles
            if (kt >= nkt - 2) {
                const int kt0 = kt * 64;
                int rq0 = q0 + warp * 16 + gr;
                int rq1 = rq0 + 8;
#pragma unroll
                for (int t = 0; t < 8; t++) {
                    int c0 = kt0 + 8 * t + 2 * tc;
                    if (c0 > rq0)     sacc[t][0] = -1e30f;
                    if (c0 + 1 > rq0) sacc[t][1] = -1e30f;
                    if (c0 > rq1)     sacc[t][2] = -1e30f;
                    if (c0 + 1 > rq1) sacc[t][3] = -1e30f;
                }
            }

            // ---- online softmax (base-2, quad reductions)
            float mx0 = -1e30f, mx1 = -1e30f;
#pragma unroll
            for (int t = 0; t < 8; t++) {
                mx0 = fmaxf(mx0, fmaxf(sacc[t][0], sacc[t][1]));
                mx1 = fmaxf(mx1, fmaxf(sacc[t][2], sacc[t][3]));
            }
            mx0 = fmaxf(mx0, __shfl_xor_sync(0xffffffffu, mx0, 1));
            mx0 = fmaxf(mx0, __shfl_xor_sync(0xffffffffu, mx0, 2));
            mx1 = fmaxf(mx1, __shfl_xor_sync(0xffffffffu, mx1, 1));
            mx1 = fmaxf(mx1, __shfl_xor_sync(0xffffffffu, mx1, 2));
            float mn0 = fmaxf(m0, mx0), mn1 = fmaxf(m1, mx1);
            float cr0 = fast_exp2(m0 - mn0), cr1 = fast_exp2(m1 - mn1);
            m0 = mn0; m1 = mn1;
            l0 *= cr0; l1 *= cr1;
#pragma unroll
            for (int t = 0; t < 8; t++) {
                oacc[t][0] *= cr0; oacc[t][1] *= cr0;
                oacc[t][2] *= cr1; oacc[t][3] *= cr1;
            }
            uint32_t phi[8][2];
            float rs0 = 0.f, rs1 = 0.f;
#pragma unroll
            for (int t = 0; t < 8; t++) {
                float p0 = fast_exp2(sacc[t][0] - m0);
                float p1 = fast_exp2(sacc[t][1] - m0);
                float p2 = fast_exp2(sacc[t][2] - m1);
                float p3 = fast_exp2(sacc[t][3] - m1);
                rs0 += p0 + p1; rs1 += p2 + p3;
                phi[t][0] = pack_f16x2(p0, p1);
                phi[t][1] = pack_f16x2(p2, p3);
            }
            rs0 += __shfl_xor_sync(0xffffffffu, rs0, 1);
            rs0 += __shfl_xor_sync(0xffffffffu, rs0, 2);
            rs1 += __shfl_xor_sync(0xffffffffu, rs1, 1);
            rs1 += __shfl_xor_sync(0xffffffffu, rs1, 2);
            l0 += rs0; l1 += rs1;

            // ---- PV: O += P.V  (V row-major; B-frags via ldmatrix.trans)
#pragma unroll
            for (int ck = 0; ck < 4; ck++) {
                uint32_t aph[4] = { phi[2 * ck][0], phi[2 * ck][1],
                                    phi[2 * ck + 1][0], phi[2 * ck + 1][1] };
                uint32_t vfr[4][4];
#pragma unroll
                for (int dt = 0; dt < 4; dt++) {
                    uint32_t addr = vs + (ck * 16 + v_row_off) * KPITCH + dt * 32 + v_coff;
                    LDMATRIX_X4_TRANS(vfr[dt][0], vfr[dt][1], vfr[dt][2], vfr[dt][3], addr);
                }
#pragma unroll
                for (int ni = 0; ni < 8; ni++)
                    MMA_F16(oacc[ni], aph[0], aph[1], aph[2], aph[3],
                            vfr[ni >> 1][(ni & 1) * 2 + 0], vfr[ni >> 1][(ni & 1) * 2 + 1]);
            }
        }

        __syncthreads();
        if (kt + 2 < nkt) load_tile(kt + 2, st);
        asm volatile("cp.async.commit_group;\n" ::: "memory");
    }

    // ---- epilogue: write plain fp16 attention output into aP [M x 1024]
    const float inv0 = 1.f / l0, inv1 = 1.f / l1;
    const int qr0 = q0 + warp * 16 + gr;
    const int qr1 = qr0 + 8;
#pragma unroll
    for (int t = 0; t < 8; t++) {
        int col = h * DHEAD + 8 * t + 2 * tc;
        *(__half2*)(aP + ((size_t)(b * SEQ + qr0)) * DMODEL + col) =
            __half2(__float2half_rn(oacc[t][0] * inv0), __float2half_rn(oacc[t][1] * inv0));
        *(__half2*)(aP + ((size_t)(b * SEQ + qr1)) * DMODEL + col) =
            __half2(__float2half_rn(oacc[t][2] * inv1), __float2half_rn(oacc[t][3] * inv1));
    }
}

// ---------------------------------------------------------------------------
extern "C" void kernel_launch(void* const* d_in, const int* in_sizes, int n_in,
                              void* d_out, int out_size)
{
    const float* x     = (const float*)d_in[0];
    const float* W_qkv = (const float*)d_in[1];
    const float* W_o   = (const float*)d_in[2];
    float* out = (float*)d_out;

    __half *aP, *w1P, *w2P, *qp, *kp, *vp;
    cudaGetSymbolAddress((void**)&aP, g_aP);
    cudaGetSymbolAddress((void**)&w1P, g_w1P);
    cudaGetSymbolAddress((void**)&w2P, g_w2P);
    cudaGetSymbolAddress((void**)&qp, g_qp);
    cudaGetSymbolAddress((void**)&kp, g_kp);
    cudaGetSymbolAddress((void**)&vp, g_vp);

    cudaFuncSetAttribute(flash_mma_kernel,
                         cudaFuncAttributeMaxDynamicSharedMemorySize, FSMEM);
    cudaFuncSetAttribute(mma_gemm_kernel,
                         cudaFuncAttributeMaxDynamicSharedMemorySize, GSMEM2);
    cudaFuncSetAttribute(mma_gemm_qkv_kernel,
                         cudaFuncAttributeMaxDynamicSharedMemorySize, GSMEM1);

    // all conversions in one launch
    conv_all_kernel<<<4096 + 3072 + 1024, 256>>>(x, W_qkv, W_o, aP, w1P, w2P);

    // 1) QKV GEMM with fused Q/K/V fp16 epilogue   (M=4096, N=3072, K=1024)
    {
        dim3 grid(QKV_COLS / 128, MROWS / 128);
        mma_gemm_qkv_kernel<<<grid, 128, GSMEM1>>>(aP, w1P, qp, kp, vp,
                                                   QKV_COLS, DMODEL);
    }
    // 2) flash attention (q-tile 128, writes fp16 aP for out-proj)
    {
        dim3 grid(SEQ / 128, NHEAD, BATCH);
        flash_mma_kernel<<<grid, 256, FSMEM>>>(qp, kp, vp, aP);
    }
    // 3) out = attn_out @ W_o   (M=4096, N=1024, K=1024)
    {
        dim3 grid(DMODEL / 128, MROWS / 128);
        mma_gemm_kernel<<<grid, 128, GSMEM2>>>(aP, w2P, out, DMODEL, DMODEL);
    }
}

// round 15
// speedup vs baseline: 1.0351x; 1.0351x over previous
#include <cuda_runtime.h>
#include <cuda_bf16.h>
#include <cuda_fp16.h>
#include <math.h>
#include <stdint.h>

// Problem constants
#define BATCH 2
#define SEQ   2048
#define DMODEL 1024
#define NHEAD 16
#define DHEAD 64
#define MROWS (BATCH * SEQ)           // 4096
#define QKV_COLS (3 * DMODEL)         // 3072
#define QSCALE 0.18033688f            // 0.125 * log2(e)

// ---------------------------------------------------------------------------
// Scratch (static device globals; allocations are forbidden)
// ---------------------------------------------------------------------------
__device__ __half g_aP[(size_t)MROWS * DMODEL];            // 8.4 MB (A fp16, both GEMMs)
__device__ __half g_w1P[(size_t)QKV_COLS * DMODEL];        // 6.3 MB (W_qkv^T fp16)
__device__ __half g_w2P[(size_t)DMODEL * DMODEL];          // 2.1 MB (W_o^T fp16)
// Attention operands (plain fp16, all [b,h,t,64])
__device__ __half g_qp[(size_t)BATCH * NHEAD * SEQ * DHEAD];  // 8.4 MB
__device__ __half g_kp[(size_t)BATCH * NHEAD * SEQ * DHEAD];  // 8.4 MB
__device__ __half g_vp[(size_t)BATCH * NHEAD * SEQ * DHEAD];  // 8.4 MB

__device__ __forceinline__ uint32_t smem_u32(const void* p) {
    uint32_t a;
    asm("{ .reg .u64 t; cvta.to.shared.u64 t, %1; cvt.u32.u64 %0, t; }" : "=r"(a) : "l"(p));
    return a;
}
__device__ __forceinline__ float fast_exp2(float x) {
    float y; asm("ex2.approx.ftz.f32 %0, %1;" : "=f"(y) : "f"(x)); return y;
}
// pack fp16x2: low half = lo, high half = hi
__device__ __forceinline__ uint32_t pack_f16x2(float lo, float hi) {
    uint32_t r; asm("cvt.rn.f16x2.f32 %0, %1, %2;" : "=r"(r) : "f"(hi), "f"(lo)); return r;
}

#define LDMATRIX_X4(r0, r1, r2, r3, addr) \
    asm volatile("ldmatrix.sync.aligned.m8n8.x4.shared.b16 {%0,%1,%2,%3}, [%4];" \
        : "=r"(r0), "=r"(r1), "=r"(r2), "=r"(r3) : "r"(addr))

#define LDMATRIX_X4_TRANS(r0, r1, r2, r3, addr) \
    asm volatile("ldmatrix.sync.aligned.m8n8.x4.trans.shared.b16 {%0,%1,%2,%3}, [%4];" \
        : "=r"(r0), "=r"(r1), "=r"(r2), "=r"(r3) : "r"(addr))

#define MMA_F16(acc, a0, a1, a2, a3, b0, b1) \
    asm volatile( \
        "mma.sync.aligned.m16n8k16.row.col.f32.f16.f16.f32 " \
        "{%0,%1,%2,%3}, {%4,%5,%6,%7}, {%8,%9}, {%0,%1,%2,%3};" \
        : "+f"((acc)[0]), "+f"((acc)[1]), "+f"((acc)[2]), "+f"((acc)[3]) \
        : "r"(a0), "r"(a1), "r"(a2), "r"(a3), "r"(b0), "r"(b1))

// ---------------------------------------------------------------------------
// Merged conversion kernel (single launch):
//   section 0: x fp32 -> aP fp16                  (4096 blocks)
//   section 1: W_qkv -> w1P transpose-cast        (3072 blocks)
//   section 2: W_o   -> w2P transpose-cast        (1024 blocks)
// ---------------------------------------------------------------------------
__global__ void __launch_bounds__(256) conv_all_kernel(
    const float* __restrict__ x, const float* __restrict__ Wq,
    const float* __restrict__ Wo,
    __half* __restrict__ aP, __half* __restrict__ w1P, __half* __restrict__ w2P)
{
    const int bid = blockIdx.x;
    const int tid = threadIdx.x;

    if (bid < 4096) {
        size_t j = (size_t)bid * 256 + tid;
        float4 v = *(const float4*)(x + 4 * j);
        __half2* o = (__half2*)(aP + 4 * j);
        o[0] = __half2(__float2half_rn(v.x), __float2half_rn(v.y));
        o[1] = __half2(__float2half_rn(v.z), __float2half_rn(v.w));
        return;
    }

    __shared__ float t[32][33];
    const int tx = tid & 31, ty = tid >> 5;
    const float* W;
    __half* out;
    int N, bx, by;
    if (bid < 4096 + 3072) {
        int idx = bid - 4096;
        W = Wq; out = w1P; N = QKV_COLS;
        bx = idx % (QKV_COLS / 32); by = idx / (QKV_COLS / 32);
    } else {
        int idx = bid - 4096 - 3072;
        W = Wo; out = w2P; N = DMODEL;
        bx = idx % (DMODEL / 32); by = idx / (DMODEL / 32);
    }
#pragma unroll
    for (int i = 0; i < 4; i++) {
        int k = by * 32 + ty + 8 * i;
        int n = bx * 32 + tx;
        t[ty + 8 * i][tx] = W[(size_t)k * N + n];
    }
    __syncthreads();
#pragma unroll
    for (int i = 0; i < 4; i++) {
        int nl = ty + 8 * i;
        int n = bx * 32 + nl;
        out[(size_t)n * DMODEL + by * 32 + tx] = __float2half_rn(t[tx][nl]);
    }
}

// ---------------------------------------------------------------------------
// Shared GEMM fragment-compute body (one k16 x2 sub-step).
// ---------------------------------------------------------------------------
#define GEMM_COMPUTE_STEP(sA, sB, ROWB_, ks)                                   \
    {                                                                          \
        uint32_t af[4][4];                                                     \
        _Pragma("unroll")                                                      \
        for (int mi = 0; mi < 4; mi++) {                                       \
            uint32_t addr = (sA) + (wm0 + mi * 16 + a_row_off) * (ROWB_) +     \
                            ((ks) * 2 + a_kch) * 16;                           \
            LDMATRIX_X4(af[mi][0], af[mi][1], af[mi][2], af[mi][3], addr);     \
        }                                                                      \
        uint32_t bfr[4][4];                                                    \
        _Pragma("unroll")                                                      \
        for (int nj = 0; nj < 4; nj++) {                                       \
            uint32_t addr = (sB) + (wn0 + nj * 16 + b_row_off) * (ROWB_) +     \
                            ((ks) * 2 + b_kch) * 16;                           \
            LDMATRIX_X4(bfr[nj][0], bfr[nj][1], bfr[nj][2], bfr[nj][3], addr); \
        }                                                                      \
        _Pragma("unroll")                                                      \
        for (int mi = 0; mi < 4; mi++)                                         \
            _Pragma("unroll")                                                  \
            for (int ni = 0; ni < 8; ni++)                                     \
                MMA_F16(acc[mi][ni], af[mi][0], af[mi][1], af[mi][2], af[mi][3], \
                        bfr[ni >> 1][(ni & 1) * 2 + 0], bfr[ni >> 1][(ni & 1) * 2 + 1]); \
    }

#define GEMM_COMMON_DECLS()                                                    \
    const int tid = threadIdx.x;                                               \
    const int warp = tid >> 5;                                                 \
    const int lane = tid & 31;                                                 \
    const int bm = blockIdx.y * 128;                                           \
    const int bn = blockIdx.x * 128;                                           \
    const int wm0 = (warp >> 1) * 64;                                          \
    const int wn0 = (warp & 1) * 64;                                           \
    const int a_row_off = (lane & 7) + ((lane >> 3) & 1) * 8;                  \
    const int a_kch = (lane >> 4);                                             \
    const int b_row_off = (lane & 7) + ((lane >> 4) & 1) * 8;                  \
    const int b_kch = (lane >> 3) & 1;                                         \
    const uint32_t sbase = smem_u32(gsm);                                      \
    float acc[4][8][4];                                                        \
    _Pragma("unroll")                                                          \
    for (int mi = 0; mi < 4; mi++)                                             \
        _Pragma("unroll")                                                      \
        for (int ni = 0; ni < 8; ni++)                                         \
            _Pragma("unroll")                                                  \
            for (int r = 0; r < 4; r++) acc[mi][ni][r] = 0.f;

// ---- BK=32, 4-stage pipeline (R13 config; for the long-K QKV GEMM) ----
#define GBK1 32
#define ROWB1 80
#define STILE1 (128 * ROWB1)         // 10240 B
#define GSTAGE1 (2 * STILE1)         // 20480 B
#define GSMEM1 (4 * GSTAGE1)         // 81920 B

#define GEMM_LOOP_BK32()                                                       \
    GEMM_COMMON_DECLS()                                                        \
    const int NIT = K / GBK1;                                                  \
    auto load_stage = [&](int st, int k0) {                                    \
        uint32_t base = sbase + st * GSTAGE1;                                  \
        _Pragma("unroll")                                                      \
        for (int i = 0; i < 4; i++) {                                          \
            int c = tid + i * 128;               /* 0..511 */                  \
            int row = c >> 2, ch = c & 3;                                      \
            uint32_t dA = base + row * ROWB1 + ch * 16;                        \
            uint32_t dB = dA + STILE1;                                         \
            const __half* pA = A + (size_t)(bm + row) * K + k0 + ch * 8;       \
            const __half* pB = B + (size_t)(bn + row) * K + k0 + ch * 8;       \
            asm volatile("cp.async.cg.shared.global [%0], [%1], 16;\n" :: "r"(dA), "l"(pA) : "memory"); \
            asm volatile("cp.async.cg.shared.global [%0], [%1], 16;\n" :: "r"(dB), "l"(pB) : "memory"); \
        }                                                                      \
    };                                                                         \
    load_stage(0, 0);                                                          \
    asm volatile("cp.async.commit_group;\n" ::: "memory");                     \
    load_stage(1, GBK1);                                                       \
    asm volatile("cp.async.commit_group;\n" ::: "memory");                     \
    load_stage(2, 2 * GBK1);                                                   \
    asm volatile("cp.async.commit_group;\n" ::: "memory");                     \
    int st = 0;                                                                \
    for (int it = 0; it < NIT; it++) {                                         \
        asm volatile("cp.async.wait_group 2;\n" ::: "memory");                 \
        __syncthreads();                                                       \
        if (it + 3 < NIT) load_stage((st + 3) & 3, (it + 3) * GBK1);           \
        asm volatile("cp.async.commit_group;\n" ::: "memory");                 \
        uint32_t sA = sbase + st * GSTAGE1;                                    \
        uint32_t sB = sA + STILE1;                                             \
        _Pragma("unroll")                                                      \
        for (int ks = 0; ks < 2; ks++) GEMM_COMPUTE_STEP(sA, sB, ROWB1, ks)    \
        st = (st + 1) & 3;                                                     \
    }

// ---- BK=64, 3-stage pipeline (R10/R14 config; for the short-K out-proj) ----
#define GBK2 64
#define ROWB2 144
#define STILE2 (128 * ROWB2)         // 18432 B
#define GSTAGE2 (2 * STILE2)         // 36864 B
#define GSMEM2 (3 * GSTAGE2)         // 110592 B

#define GEMM_LOOP_BK64()                                                       \
    GEMM_COMMON_DECLS()                                                        \
    const int NIT = K / GBK2;                                                  \
    auto load_stage = [&](int st, int k0) {                                    \
        uint32_t base = sbase + st * GSTAGE2;                                  \
        _Pragma("unroll")                                                      \
        for (int i = 0; i < 8; i++) {                                          \
            int c = tid + i * 128;               /* 0..1023 */                 \
            int row = c >> 3, ch = c & 7;                                      \
            uint32_t dA = base + row * ROWB2 + ch * 16;                        \
            uint32_t dB = dA + STILE2;                                         \
            const __half* pA = A + (size_t)(bm + row) * K + k0 + ch * 8;       \
            const __half* pB = B + (size_t)(bn + row) * K + k0 + ch * 8;       \
            asm volatile("cp.async.cg.shared.global [%0], [%1], 16;\n" :: "r"(dA), "l"(pA) : "memory"); \
            asm volatile("cp.async.cg.shared.global [%0], [%1], 16;\n" :: "r"(dB), "l"(pB) : "memory"); \
        }                                                                      \
    };                                                                         \
    load_stage(0, 0);                                                          \
    asm volatile("cp.async.commit_group;\n" ::: "memory");                     \
    load_stage(1, GBK2);                                                       \
    asm volatile("cp.async.commit_group;\n" ::: "memory");                     \
    int st = 0;                                                                \
    for (int it = 0; it < NIT; it++) {                                         \
        asm volatile("cp.async.wait_group 1;\n" ::: "memory");                 \
        __syncthreads();                                                       \
        if (it + 2 < NIT) {                                                    \
            int st2 = st + 2 >= 3 ? st - 1 : st + 2;                           \
            load_stage(st2, (it + 2) * GBK2);                                  \
        }                                                                      \
        asm volatile("cp.async.commit_group;\n" ::: "memory");                 \
        uint32_t sA = sbase + st * GSTAGE2;                                    \
        uint32_t sB = sA + STILE2;                                             \
        _Pragma("unroll")                                                      \
        for (int ks = 0; ks < 4; ks++) GEMM_COMPUTE_STEP(sA, sB, ROWB2, ks)    \
        st = (st + 1 == 3) ? 0 : st + 1;                                       \
    }

// ---------------------------------------------------------------------------
// GEMM #2 (out-projection): BK=64/3-stage, plain fp32 epilogue.
// ---------------------------------------------------------------------------
__global__ void __launch_bounds__(128, 2) mma_gemm_kernel(
    const __half* __restrict__ A, const __half* __restrict__ B,
    float* __restrict__ C, int N, int K)
{
    extern __shared__ char gsm[];
    GEMM_LOOP_BK64()

    const int gr = lane >> 2;
    const int tc = (lane & 3) * 2;
#pragma unroll
    for (int mi = 0; mi < 4; mi++) {
#pragma unroll
        for (int ni = 0; ni < 8; ni++) {
            size_t r0 = (size_t)(bm + wm0 + mi * 16 + gr);
            int col = bn + wn0 + ni * 8 + tc;
            *(float2*)&C[r0 * N + col] = make_float2(acc[mi][ni][0], acc[mi][ni][1]);
            *(float2*)&C[(r0 + 8) * N + col] = make_float2(acc[mi][ni][2], acc[mi][ni][3]);
        }
    }
}

// ---------------------------------------------------------------------------
// GEMM #1 (QKV): BK=32/4-stage, fused epilogue writes fp16 Q (scaled)/K/V.
// bn in [0,1024) -> Q, [1024,2048) -> K, [2048,3072) -> V.
// ---------------------------------------------------------------------------
__global__ void __launch_bounds__(128, 2) mma_gemm_qkv_kernel(
    const __half* __restrict__ A, const __half* __restrict__ B,
    __half* __restrict__ qp, __half* __restrict__ kp,
    __half* __restrict__ vp, int N, int K)
{
    extern __shared__ char gsm[];
    GEMM_LOOP_BK32()

    const int gr = lane >> 2;
    const int tc = (lane & 3) * 2;
    const int sec = bn >> 10;                 // 0=Q, 1=K, 2=V
    const int colbase = (bn & 1023) + wn0;
    __half* const dst = (sec == 0) ? qp : ((sec == 1) ? kp : vp);

#pragma unroll
    for (int mi = 0; mi < 4; mi++) {
#pragma unroll
        for (int rr = 0; rr < 2; rr++) {
            const int row = bm + wm0 + mi * 16 + gr + rr * 8;
            const int b = row >> 11;
            const int t = row & (SEQ - 1);
#pragma unroll
            for (int ni = 0; ni < 8; ni++) {
                const int col = colbase + ni * 8 + tc;    // within section
                float v0 = acc[mi][ni][rr * 2 + 0];
                float v1 = acc[mi][ni][rr * 2 + 1];
                if (sec == 0) { v0 *= QSCALE; v1 *= QSCALE; }
                const int h = col >> 6;
                const int d = col & 63;
                size_t base = ((size_t)((b * NHEAD + h) * SEQ + t)) * DHEAD + d;
                *(__half2*)(dst + base) =
                    __half2(__float2half_rn(v0), __float2half_rn(v1));
            }
        }
    }
}

// ---------------------------------------------------------------------------
// Tensor-core flash attention (FA2), causal, plain fp16.
// CTA: 128 queries x 1 head; 8 warps (each m16 x 64-key tile), 256 threads.
// Q has its own smem region; prologue overlaps Q + K/V tile 0 + tile 1 loads.
// Fully-masked diagonal warps skip compute (bit-identical; their P was 0).
// ---------------------------------------------------------------------------
#define KPITCH 144                  // 64 fp16 = 128B data + 16 pad
#define KS_BYTES (64 * KPITCH)      // 9216
#define FSTAGE (2 * KS_BYTES)       // 18432 (K + V)
#define QS_BYTES (128 * KPITCH)     // 18432 (Q region)
#define FSMEM (2 * FSTAGE + QS_BYTES)  // 55296

__global__ void __launch_bounds__(256, 2) flash_mma_kernel(
    const __half* __restrict__ qp, const __half* __restrict__ kp,
    const __half* __restrict__ vp,
    __half* __restrict__ aP)
{
    extern __shared__ char fsm[];
    const int tid = threadIdx.x;
    const int warp = tid >> 5;
    const int lane = tid & 31;
    const int qt = gridDim.x - 1 - blockIdx.x;      // heavy tiles first
    const int h = blockIdx.y;
    const int b = blockIdx.z;
    const int bh = b * NHEAD + h;
    const int q0 = qt * 128;

    const uint32_t sb = smem_u32(fsm);
    const uint32_t qb = sb + 2 * FSTAGE;            // Q region
    const int gr = lane >> 2;
    const int tc = lane & 3;
    const int a_row_off = (lane & 7) + ((lane >> 3) & 1) * 8;
    const int a_kch = lane >> 4;
    const int b_row_off = (lane & 7) + ((lane >> 4) & 1) * 8;
    const int b_kch = (lane >> 3) & 1;
    // trans-ldmatrix addressing for V (row-major [key][d] tile)
    const int v_row_off = lane & 15;            // key within k16 chunk
    const int v_coff = (lane >> 4) * 16;        // d-half byte offset

    const int nkt = 2 * qt + 2;                 // k-tiles (64 keys each)

    auto load_tile = [&](int kt, int st) {
        const int kt0 = kt * 64;
        uint32_t ks = sb + st * FSTAGE;
        uint32_t vs = ks + KS_BYTES;
        const __half* ksrc = kp + ((size_t)(bh * SEQ + kt0)) * DHEAD;
        const __half* vsrc = vp + ((size_t)(bh * SEQ + kt0)) * DHEAD;
#pragma unroll
        for (int i = 0; i < 2; i++) {
            int c = i * 256 + tid;               // 0..511
            int row = c >> 3, ch = c & 7;
            uint32_t dk = ks + row * KPITCH + ch * 16;
            uint32_t dv = vs + row * KPITCH + ch * 16;
            const __half* sk = ksrc + (size_t)row * DHEAD + ch * 8;
            const __half* sv = vsrc + (size_t)row * DHEAD + ch * 8;
            asm volatile("cp.async.cg.shared.global [%0], [%1], 16;\n" :: "r"(dk), "l"(sk) : "memory");
            asm volatile("cp.async.cg.shared.global [%0], [%1], 16;\n" :: "r"(dv), "l"(sv) : "memory");
        }
    };

    // ---- overlapped prologue: Q + K/V tile 0 + K/V tile 1, then one wait
    {
        const __half* qsrc = qp + ((size_t)(bh * SEQ + q0)) * DHEAD;
#pragma unroll
        for (int i = 0; i < 4; i++) {
            int c = i * 256 + tid;               // 0..1023 (16B chunks)
            int row = c >> 3, ch = c & 7;
            uint32_t dst = qb + row * KPITCH + ch * 16;
            const __half* src = qsrc + (size_t)row * DHEAD + ch * 8;
            asm volatile("cp.async.cg.shared.global [%0], [%1], 16;\n" :: "r"(dst), "l"(src) : "memory");
        }
        asm volatile("cp.async.commit_group;\n" ::: "memory");
    }
    load_tile(0, 0);
    asm volatile("cp.async.commit_group;\n" ::: "memory");
    load_tile(1, 1);
    asm volatile("cp.async.commit_group;\n" ::: "memory");

    // Q group done when <=2 groups pending
    asm volatile("cp.async.wait_group 2;\n" ::: "memory");
    __syncthreads();

    uint32_t qf[4][4];
#pragma unroll
    for (int ck = 0; ck < 4; ck++) {
        uint32_t addr = qb + (warp * 16 + a_row_off) * KPITCH + ck * 32 + a_kch * 16;
        LDMATRIX_X4(qf[ck][0], qf[ck][1], qf[ck][2], qf[ck][3], addr);
    }

    float oacc[8][4];
#pragma unroll
    for (int t = 0; t < 8; t++)
#pragma unroll
        for (int r = 0; r < 4; r++) oacc[t][r] = 0.f;
    float m0 = -1e30f, m1 = -1e30f, l0 = 0.f, l1 = 0.f;

    for (int kt = 0; kt < nkt; kt++) {
        asm volatile("cp.async.wait_group 1;\n" ::: "memory");
        __syncthreads();
        const int st = kt & 1;
        uint32_t ks = sb + st * FSTAGE;
        uint32_t vs = ks + KS_BYTES;

        // warps 0-3 on the last k-tile are fully above the diagonal:
        // their P is exactly 0 there, so skip the compute entirely.
        const bool active = !(kt == nkt - 1 && warp < 4);
        if (active) {
            // ---- S = Q.K^T  (4 k16 chunks over DHEAD=64)
            float sacc[8][4];
#pragma unroll
            for (int t = 0; t < 8; t++)
#pragma unroll
                for (int r = 0; r < 4; r++) sacc[t][r] = 0.f;
#pragma unroll
            for (int ck = 0; ck < 4; ck++) {
                uint32_t bfr[4][4];
#pragma unroll
                for (int nj = 0; nj < 4; nj++) {
                    uint32_t addr = ks + (nj * 16 + b_row_off) * KPITCH + ck * 32 + b_kch * 16;
                    LDMATRIX_X4(bfr[nj][0], bfr[nj][1], bfr[nj][2], bfr[nj][3], addr);
                }
#pragma unroll
                for (int ni = 0; ni < 8; ni++)
                    MMA_F16(sacc[ni], qf[ck][0], qf[ck][1], qf[ck][2], qf[ck][3],
                            bfr[ni >> 1][(ni & 1) * 2 + 0], bfr[ni >> 1][(ni & 1) * 2 + 1]);
            }

            // ---- causal mask on the two diagonal-spanning k-tiles
            if (kt >= nkt - 2) {
                const int kt0 = kt * 64;
                int rq0 = q0 + warp * 16 + gr;
                int rq1 = rq0 + 8;
#pragma unroll
                for (int t = 0; t < 8; t++) {
                    int c0 = kt0 + 8 * t + 2 * tc;
                    if (c0 > rq0)     sacc[t][0] = -1e30f;
                    if (c0 + 1 > rq0) sacc[t][1] = -1e30f;
                    if (c0 > rq1)     sacc[t][2] = -1e30f;
                    if (c0 + 1 > rq1) sacc[t][3] = -1e30f;
                }
            }

            // ---- online softmax (base-2, quad reductions)
            float mx0 = -1e30f, mx1 = -1e30f;
#pragma unroll
            for (int t = 0; t < 8; t++) {
                mx0 = fmaxf(mx0, fmaxf(sacc[t][0], sacc[t][1]));
                mx1 = fmaxf(mx1, fmaxf(sacc[t][2], sacc[t][3]));
            }
            mx0 = fmaxf(mx0, __shfl_xor_sync(0xffffffffu, mx0, 1));
            mx0 = fmaxf(mx0, __shfl_xor_sync(0xffffffffu, mx0, 2));
            mx1 = fmaxf(mx1, __shfl_xor_sync(0xffffffffu, mx1, 1));
            mx1 = fmaxf(mx1, __shfl_xor_sync(0xffffffffu, mx1, 2));
            float mn0 = fmaxf(m0, mx0), mn1 = fmaxf(m1, mx1);
            float cr0 = fast_exp2(m0 - mn0), cr1 = fast_exp2(m1 - mn1);
            m0 = mn0; m1 = mn1;
            l0 *= cr0; l1 *= cr1;
#pragma unroll
            for (int t = 0; t < 8; t++) {
                oacc[t][0] *= cr0; oacc[t][1] *= cr0;
                oacc[t][2] *= cr1; oacc[t][3] *= cr1;
            }
            uint32_t phi[8][2];
            float rs0 = 0.f, rs1 = 0.f;
#pragma unroll
            for (int t = 0; t < 8; t++) {
                float p0 = fast_exp2(sacc[t][0] - m0);
                float p1 = fast_exp2(sacc[t][1] - m0);
                float p2 = fast_exp2(sacc[t][2] - m1);
                float p3 = fast_exp2(sacc[t][3] - m1);
                rs0 += p0 + p1; rs1 += p2 + p3;
                phi[t][0] = pack_f16x2(p0, p1);
                phi[t][1] = pack_f16x2(p2, p3);
            }
            rs0 += __shfl_xor_sync(0xffffffffu, rs0, 1);
            rs0 += __shfl_xor_sync(0xffffffffu, rs0, 2);
            rs1 += __shfl_xor_sync(0xffffffffu, rs1, 1);
            rs1 += __shfl_xor_sync(0xffffffffu, rs1, 2);
            l0 += rs0; l1 += rs1;

            // ---- PV: O += P.V  (V row-major; B-frags via ldmatrix.trans)
#pragma unroll
            for (int ck = 0; ck < 4; ck++) {
                uint32_t aph[4] = { phi[2 * ck][0], phi[2 * ck][1],
                                    phi[2 * ck + 1][0], phi[2 * ck + 1][1] };
                uint32_t vfr[4][4];
#pragma unroll
                for (int dt = 0; dt < 4; dt++) {
                    uint32_t addr = vs + (ck * 16 + v_row_off) * KPITCH + dt * 32 + v_coff;
                    LDMATRIX_X4_TRANS(vfr[dt][0], vfr[dt][1], vfr[dt][2], vfr[dt][3], addr);
                }
#pragma unroll
                for (int ni = 0; ni < 8; ni++)
                    MMA_F16(oacc[ni], aph[0], aph[1], aph[2], aph[3],
                            vfr[ni >> 1][(ni & 1) * 2 + 0], vfr[ni >> 1][(ni & 1) * 2 + 1]);
            }
        }

        __syncthreads();
        if (kt + 2 < nkt) load_tile(kt + 2, st);
        asm volatile("cp.async.commit_group;\n" ::: "memory");
    }

    // ---- epilogue: write plain fp16 attention output into aP [M x 1024]
    const float inv0 = 1.f / l0, inv1 = 1.f / l1;
    const int qr0 = q0 + warp * 16 + gr;
    const int qr1 = qr0 + 8;
#pragma unroll
    for (int t = 0; t < 8; t++) {
        int col = h * DHEAD + 8 * t + 2 * tc;
        *(__half2*)(aP + ((size_t)(b * SEQ + qr0)) * DMODEL + col) =
            __half2(__float2half_rn(oacc[t][0] * inv0), __float2half_rn(oacc[t][1] * inv0));
        *(__half2*)(aP + ((size_t)(b * SEQ + qr1)) * DMODEL + col) =
            __half2(__float2half_rn(oacc[t][2] * inv1), __float2half_rn(oacc[t][3] * inv1));
    }
}

// ---------------------------------------------------------------------------
extern "C" void kernel_launch(void* const* d_in, const int* in_sizes, int n_in,
                              void* d_out, int out_size)
{
    const float* x     = (const float*)d_in[0];
    const float* W_qkv = (const float*)d_in[1];
    const float* W_o   = (const float*)d_in[2];
    float* out = (float*)d_out;

    __half *aP, *w1P, *w2P, *qp, *kp, *vp;
    cudaGetSymbolAddress((void**)&aP, g_aP);
    cudaGetSymbolAddress((void**)&w1P, g_w1P);
    cudaGetSymbolAddress((void**)&w2P, g_w2P);
    cudaGetSymbolAddress((void**)&qp, g_qp);
    cudaGetSymbolAddress((void**)&kp, g_kp);
    cudaGetSymbolAddress((void**)&vp, g_vp);

    cudaFuncSetAttribute(flash_mma_kernel,
                         cudaFuncAttributeMaxDynamicSharedMemorySize, FSMEM);
    cudaFuncSetAttribute(mma_gemm_kernel,
                         cudaFuncAttributeMaxDynamicSharedMemorySize, GSMEM2);
    cudaFuncSetAttribute(mma_gemm_qkv_kernel,
                         cudaFuncAttributeMaxDynamicSharedMemorySize, GSMEM1);

    // all conversions in one launch
    conv_all_kernel<<<4096 + 3072 + 1024, 256>>>(x, W_qkv, W_o, aP, w1P, w2P);

    // 1) QKV GEMM with fused Q/K/V fp16 epilogue   (M=4096, N=3072, K=1024)
    {
        dim3 grid(QKV_COLS / 128, MROWS / 128);
        mma_gemm_qkv_kernel<<<grid, 128, GSMEM1>>>(aP, w1P, qp, kp, vp,
                                                   QKV_COLS, DMODEL);
    }
    // 2) flash attention (q-tile 128, writes fp16 aP for out-proj)
    {
        dim3 grid(SEQ / 128, NHEAD, BATCH);
        flash_mma_kernel<<<grid, 256, FSMEM>>>(qp, kp, vp, aP);
    }
    // 3) out = attn_out @ W_o   (M=4096, N=1024, K=1024)
    {
        dim3 grid(DMODEL / 128, MROWS / 128);
        mma_gemm_kernel<<<grid, 128, GSMEM2>>>(aP, w2P, out, DMODEL, DMODEL);
    }
}

// round 16
// speedup vs baseline: 1.0372x; 1.0020x over previous
#include <cuda_runtime.h>
#include <cuda_bf16.h>
#include <cuda_fp16.h>
#include <math.h>
#include <stdint.h>

// Problem constants
#define BATCH 2
#define SEQ   2048
#define DMODEL 1024
#define NHEAD 16
#define DHEAD 64
#define MROWS (BATCH * SEQ)           // 4096
#define QKV_COLS (3 * DMODEL)         // 3072
#define QSCALE 0.18033688f            // 0.125 * log2(e)

// ---------------------------------------------------------------------------
// Scratch (static device globals; allocations are forbidden)
// ---------------------------------------------------------------------------
__device__ __half g_aP[(size_t)MROWS * DMODEL];            // 8.4 MB (A fp16, both GEMMs)
__device__ __half g_w1P[(size_t)QKV_COLS * DMODEL];        // 6.3 MB (W_qkv^T fp16)
__device__ __half g_w2P[(size_t)DMODEL * DMODEL];          // 2.1 MB (W_o^T fp16)
// Attention operands (plain fp16, all [b,h,t,64])
__device__ __half g_qp[(size_t)BATCH * NHEAD * SEQ * DHEAD];  // 8.4 MB
__device__ __half g_kp[(size_t)BATCH * NHEAD * SEQ * DHEAD];  // 8.4 MB
__device__ __half g_vp[(size_t)BATCH * NHEAD * SEQ * DHEAD];  // 8.4 MB

__device__ __forceinline__ uint32_t smem_u32(const void* p) {
    uint32_t a;
    asm("{ .reg .u64 t; cvta.to.shared.u64 t, %1; cvt.u32.u64 %0, t; }" : "=r"(a) : "l"(p));
    return a;
}
__device__ __forceinline__ float fast_exp2(float x) {
    float y; asm("ex2.approx.ftz.f32 %0, %1;" : "=f"(y) : "f"(x)); return y;
}
// pack fp16x2: low half = lo, high half = hi
__device__ __forceinline__ uint32_t pack_f16x2(float lo, float hi) {
    uint32_t r; asm("cvt.rn.f16x2.f32 %0, %1, %2;" : "=r"(r) : "f"(hi), "f"(lo)); return r;
}

#define LDMATRIX_X4(r0, r1, r2, r3, addr) \
    asm volatile("ldmatrix.sync.aligned.m8n8.x4.shared.b16 {%0,%1,%2,%3}, [%4];" \
        : "=r"(r0), "=r"(r1), "=r"(r2), "=r"(r3) : "r"(addr))

#define LDMATRIX_X4_TRANS(r0, r1, r2, r3, addr) \
    asm volatile("ldmatrix.sync.aligned.m8n8.x4.trans.shared.b16 {%0,%1,%2,%3}, [%4];" \
        : "=r"(r0), "=r"(r1), "=r"(r2), "=r"(r3) : "r"(addr))

#define MMA_F16(acc, a0, a1, a2, a3, b0, b1) \
    asm volatile( \
        "mma.sync.aligned.m16n8k16.row.col.f32.f16.f16.f32 " \
        "{%0,%1,%2,%3}, {%4,%5,%6,%7}, {%8,%9}, {%0,%1,%2,%3};" \
        : "+f"((acc)[0]), "+f"((acc)[1]), "+f"((acc)[2]), "+f"((acc)[3]) \
        : "r"(a0), "r"(a1), "r"(a2), "r"(a3), "r"(b0), "r"(b1))

// ---------------------------------------------------------------------------
// Merged conversion kernel (single launch):
//   section 0: x fp32 -> aP fp16                  (4096 blocks)
//   section 1: W_qkv -> w1P transpose-cast        (3072 blocks)
//   section 2: W_o   -> w2P transpose-cast        (1024 blocks)
// Weight sections store vectorized __half2 (128B/warp).
// ---------------------------------------------------------------------------
__global__ void __launch_bounds__(256) conv_all_kernel(
    const float* __restrict__ x, const float* __restrict__ Wq,
    const float* __restrict__ Wo,
    __half* __restrict__ aP, __half* __restrict__ w1P, __half* __restrict__ w2P)
{
    const int bid = blockIdx.x;
    const int tid = threadIdx.x;

    if (bid < 4096) {
        size_t j = (size_t)bid * 256 + tid;
        float4 v = *(const float4*)(x + 4 * j);
        __half2* o = (__half2*)(aP + 4 * j);
        o[0] = __half2(__float2half_rn(v.x), __float2half_rn(v.y));
        o[1] = __half2(__float2half_rn(v.z), __float2half_rn(v.w));
        return;
    }

    __shared__ float t[32][33];
    const int tx = tid & 31, ty = tid >> 5;
    const float* W;
    __half* out;
    int N, bx, by;
    if (bid < 4096 + 3072) {
        int idx = bid - 4096;
        W = Wq; out = w1P; N = QKV_COLS;
        bx = idx % (QKV_COLS / 32); by = idx / (QKV_COLS / 32);
    } else {
        int idx = bid - 4096 - 3072;
        W = Wo; out = w2P; N = DMODEL;
        bx = idx % (DMODEL / 32); by = idx / (DMODEL / 32);
    }
#pragma unroll
    for (int i = 0; i < 4; i++) {
        int k = by * 32 + ty + 8 * i;
        int n = bx * 32 + tx;
        t[ty + 8 * i][tx] = W[(size_t)k * N + n];
    }
    __syncthreads();
    // vectorized write: 512 __half2 per block = 256 threads x 2
#pragma unroll
    for (int i = 0; i < 2; i++) {
        int idx = tid + i * 256;          // 0..511
        int nl = idx >> 4;                // 0..31 (output row = W column)
        int kk = idx & 15;                // pair index within 32 k's
        __half2 v = __half2(__float2half_rn(t[2 * kk][nl]),
                            __float2half_rn(t[2 * kk + 1][nl]));
        *(__half2*)&out[(size_t)(bx * 32 + nl) * DMODEL + by * 32 + 2 * kk] = v;
    }
}

// ---------------------------------------------------------------------------
// Shared GEMM fragment-compute body (one k16 x2 sub-step).
// ---------------------------------------------------------------------------
#define GEMM_COMPUTE_STEP(sA, sB, ROWB_, ks)                                   \
    {                                                                          \
        uint32_t af[4][4];                                                     \
        _Pragma("unroll")                                                      \
        for (int mi = 0; mi < 4; mi++) {                                       \
            uint32_t addr = (sA) + (wm0 + mi * 16 + a_row_off) * (ROWB_) +     \
                            ((ks) * 2 + a_kch) * 16;                           \
            LDMATRIX_X4(af[mi][0], af[mi][1], af[mi][2], af[mi][3], addr);     \
        }                                                                      \
        uint32_t bfr[4][4];                                                    \
        _Pragma("unroll")                                                      \
        for (int nj = 0; nj < 4; nj++) {                                       \
            uint32_t addr = (sB) + (wn0 + nj * 16 + b_row_off) * (ROWB_) +     \
                            ((ks) * 2 + b_kch) * 16;                           \
            LDMATRIX_X4(bfr[nj][0], bfr[nj][1], bfr[nj][2], bfr[nj][3], addr); \
        }                                                                      \
        _Pragma("unroll")                                                      \
        for (int mi = 0; mi < 4; mi++)                                         \
            _Pragma("unroll")                                                  \
            for (int ni = 0; ni < 8; ni++)                                     \
                MMA_F16(acc[mi][ni], af[mi][0], af[mi][1], af[mi][2], af[mi][3], \
                        bfr[ni >> 1][(ni & 1) * 2 + 0], bfr[ni >> 1][(ni & 1) * 2 + 1]); \
    }

#define GEMM_COMMON_DECLS()                                                    \
    const int tid = threadIdx.x;                                               \
    const int warp = tid >> 5;                                                 \
    const int lane = tid & 31;                                                 \
    const int bm = blockIdx.y * 128;                                           \
    const int bn = blockIdx.x * 128;                                           \
    const int wm0 = (warp >> 1) * 64;                                          \
    const int wn0 = (warp & 1) * 64;                                           \
    const int a_row_off = (lane & 7) + ((lane >> 3) & 1) * 8;                  \
    const int a_kch = (lane >> 4);                                             \
    const int b_row_off = (lane & 7) + ((lane >> 4) & 1) * 8;                  \
    const int b_kch = (lane >> 3) & 1;                                         \
    const uint32_t sbase = smem_u32(gsm);                                      \
    float acc[4][8][4];                                                        \
    _Pragma("unroll")                                                          \
    for (int mi = 0; mi < 4; mi++)                                             \
        _Pragma("unroll")                                                      \
        for (int ni = 0; ni < 8; ni++)                                         \
            _Pragma("unroll")                                                  \
            for (int r = 0; r < 4; r++) acc[mi][ni][r] = 0.f;

// ---- BK=32, 4-stage pipeline (for the long-K QKV GEMM) ----
#define GBK1 32
#define ROWB1 80
#define STILE1 (128 * ROWB1)         // 10240 B
#define GSTAGE1 (2 * STILE1)         // 20480 B
#define GSMEM1 (4 * GSTAGE1)         // 81920 B

#define GEMM_LOOP_BK32()                                                       \
    GEMM_COMMON_DECLS()                                                        \
    const int NIT = K / GBK1;                                                  \
    auto load_stage = [&](int st, int k0) {                                    \
        uint32_t base = sbase + st * GSTAGE1;                                  \
        _Pragma("unroll")                                                      \
        for (int i = 0; i < 4; i++) {                                          \
            int c = tid + i * 128;               /* 0..511 */                  \
            int row = c >> 2, ch = c & 3;                                      \
            uint32_t dA = base + row * ROWB1 + ch * 16;                        \
            uint32_t dB = dA + STILE1;                                         \
            const __half* pA = A + (size_t)(bm + row) * K + k0 + ch * 8;       \
            const __half* pB = B + (size_t)(bn + row) * K + k0 + ch * 8;       \
            asm volatile("cp.async.cg.shared.global [%0], [%1], 16;\n" :: "r"(dA), "l"(pA) : "memory"); \
            asm volatile("cp.async.cg.shared.global [%0], [%1], 16;\n" :: "r"(dB), "l"(pB) : "memory"); \
        }                                                                      \
    };                                                                         \
    load_stage(0, 0);                                                          \
    asm volatile("cp.async.commit_group;\n" ::: "memory");                     \
    load_stage(1, GBK1);                                                       \
    asm volatile("cp.async.commit_group;\n" ::: "memory");                     \
    load_stage(2, 2 * GBK1);                                                   \
    asm volatile("cp.async.commit_group;\n" ::: "memory");                     \
    int st = 0;                                                                \
    for (int it = 0; it < NIT; it++) {                                         \
        asm volatile("cp.async.wait_group 2;\n" ::: "memory");                 \
        __syncthreads();                                                       \
        if (it + 3 < NIT) load_stage((st + 3) & 3, (it + 3) * GBK1);           \
        asm volatile("cp.async.commit_group;\n" ::: "memory");                 \
        uint32_t sA = sbase + st * GSTAGE1;                                    \
        uint32_t sB = sA + STILE1;                                             \
        _Pragma("unroll")                                                      \
        for (int ks = 0; ks < 2; ks++) GEMM_COMPUTE_STEP(sA, sB, ROWB1, ks)    \
        st = (st + 1) & 3;                                                     \
    }

// ---- BK=64, 3-stage pipeline (for the short-K out-projection) ----
#define GBK2 64
#define ROWB2 144
#define STILE2 (128 * ROWB2)         // 18432 B
#define GSTAGE2 (2 * STILE2)         // 36864 B
#define GSMEM2 (3 * GSTAGE2)         // 110592 B

#define GEMM_LOOP_BK64()                                                       \
    GEMM_COMMON_DECLS()                                                        \
    const int NIT = K / GBK2;                                                  \
    auto load_stage = [&](int st, int k0) {                                    \
        uint32_t base = sbase + st * GSTAGE2;                                  \
        _Pragma("unroll")                                                      \
        for (int i = 0; i < 8; i++) {                                          \
            int c = tid + i * 128;               /* 0..1023 */                 \
            int row = c >> 3, ch = c & 7;                                      \
            uint32_t dA = base + row * ROWB2 + ch * 16;                        \
            uint32_t dB = dA + STILE2;                                         \
            const __half* pA = A + (size_t)(bm + row) * K + k0 + ch * 8;       \
            const __half* pB = B + (size_t)(bn + row) * K + k0 + ch * 8;       \
            asm volatile("cp.async.cg.shared.global [%0], [%1], 16;\n" :: "r"(dA), "l"(pA) : "memory"); \
            asm volatile("cp.async.cg.shared.global [%0], [%1], 16;\n" :: "r"(dB), "l"(pB) : "memory"); \
        }                                                                      \
    };                                                                         \
    load_stage(0, 0);                                                          \
    asm volatile("cp.async.commit_group;\n" ::: "memory");                     \
    load_stage(1, GBK2);                                                       \
    asm volatile("cp.async.commit_group;\n" ::: "memory");                     \
    int st = 0;                                                                \
    for (int it = 0; it < NIT; it++) {                                         \
        asm volatile("cp.async.wait_group 1;\n" ::: "memory");                 \
        __syncthreads();                                                       \
        if (it + 2 < NIT) {                                                    \
            int st2 = st + 2 >= 3 ? st - 1 : st + 2;                           \
            load_stage(st2, (it + 2) * GBK2);                                  \
        }                                                                      \
        asm volatile("cp.async.commit_group;\n" ::: "memory");                 \
        uint32_t sA = sbase + st * GSTAGE2;                                    \
        uint32_t sB = sA + STILE2;                                             \
        _Pragma("unroll")                                                      \
        for (int ks = 0; ks < 4; ks++) GEMM_COMPUTE_STEP(sA, sB, ROWB2, ks)    \
        st = (st + 1 == 3) ? 0 : st + 1;                                       \
    }

// ---------------------------------------------------------------------------
// GEMM #2 (out-projection): BK=64/3-stage, plain fp32 epilogue.
// ---------------------------------------------------------------------------
__global__ void __launch_bounds__(128, 2) mma_gemm_kernel(
    const __half* __restrict__ A, const __half* __restrict__ B,
    float* __restrict__ C, int N, int K)
{
    extern __shared__ char gsm[];
    GEMM_LOOP_BK64()

    const int gr = lane >> 2;
    const int tc = (lane & 3) * 2;
#pragma unroll
    for (int mi = 0; mi < 4; mi++) {
#pragma unroll
        for (int ni = 0; ni < 8; ni++) {
            size_t r0 = (size_t)(bm + wm0 + mi * 16 + gr);
            int col = bn + wn0 + ni * 8 + tc;
            *(float2*)&C[r0 * N + col] = make_float2(acc[mi][ni][0], acc[mi][ni][1]);
            *(float2*)&C[(r0 + 8) * N + col] = make_float2(acc[mi][ni][2], acc[mi][ni][3]);
        }
    }
}

// ---------------------------------------------------------------------------
// GEMM #1 (QKV): BK=32/4-stage, fused epilogue writes fp16 Q (scaled)/K/V.
// bn in [0,1024) -> Q, [1024,2048) -> K, [2048,3072) -> V.
// ---------------------------------------------------------------------------
__global__ void __launch_bounds__(128, 2) mma_gemm_qkv_kernel(
    const __half* __restrict__ A, const __half* __restrict__ B,
    __half* __restrict__ qp, __half* __restrict__ kp,
    __half* __restrict__ vp, int N, int K)
{
    extern __shared__ char gsm[];
    GEMM_LOOP_BK32()

    const int gr = lane >> 2;
    const int tc = (lane & 3) * 2;
    const int sec = bn >> 10;                 // 0=Q, 1=K, 2=V
    const int colbase = (bn & 1023) + wn0;
    __half* const dst = (sec == 0) ? qp : ((sec == 1) ? kp : vp);

#pragma unroll
    for (int mi = 0; mi < 4; mi++) {
#pragma unroll
        for (int rr = 0; rr < 2; rr++) {
            const int row = bm + wm0 + mi * 16 + gr + rr * 8;
            const int b = row >> 11;
            const int t = row & (SEQ - 1);
#pragma unroll
            for (int ni = 0; ni < 8; ni++) {
                const int col = colbase + ni * 8 + tc;    // within section
                float v0 = acc[mi][ni][rr * 2 + 0];
                float v1 = acc[mi][ni][rr * 2 + 1];
                if (sec == 0) { v0 *= QSCALE; v1 *= QSCALE; }
                const int h = col >> 6;
                const int d = col & 63;
                size_t base = ((size_t)((b * NHEAD + h) * SEQ + t)) * DHEAD + d;
                *(__half2*)(dst + base) =
                    __half2(__float2half_rn(v0), __float2half_rn(v1));
            }
        }
    }
}

// ---------------------------------------------------------------------------
// Tensor-core flash attention (FA2), causal, plain fp16.
// CTA: 128 queries x 1 head; 8 warps (each m16 x 64-key tile), 256 threads.
// Q has its own smem region; prologue overlaps Q + K/V tile 0 + tile 1 loads.
// Fully-masked diagonal warps skip compute (bit-identical; their P was 0).
// ---------------------------------------------------------------------------
#define KPITCH 144                  // 64 fp16 = 128B data + 16 pad
#define KS_BYTES (64 * KPITCH)      // 9216
#define FSTAGE (2 * KS_BYTES)       // 18432 (K + V)
#define QS_BYTES (128 * KPITCH)     // 18432 (Q region)
#define FSMEM (2 * FSTAGE + QS_BYTES)  // 55296

__global__ void __launch_bounds__(256, 2) flash_mma_kernel(
    const __half* __restrict__ qp, const __half* __restrict__ kp,
    const __half* __restrict__ vp,
    __half* __restrict__ aP)
{
    extern __shared__ char fsm[];
    const int tid = threadIdx.x;
    const int warp = tid >> 5;
    const int lane = tid & 31;
    const int qt = gridDim.x - 1 - blockIdx.x;      // heavy tiles first
    const int h = blockIdx.y;
    const int b = blockIdx.z;
    const int bh = b * NHEAD + h;
    const int q0 = qt * 128;

    const uint32_t sb = smem_u32(fsm);
    const uint32_t qb = sb + 2 * FSTAGE;            // Q region
    const int gr = lane >> 2;
    const int tc = lane & 3;
    const int a_row_off = (lane & 7) + ((lane >> 3) & 1) * 8;
    const int a_kch = lane >> 4;
    const int b_row_off = (lane & 7) + ((lane >> 4) & 1) * 8;
    const int b_kch = (lane >> 3) & 1;
    // trans-ldmatrix addressing for V (row-major [key][d] tile)
    const int v_row_off = lane & 15;            // key within k16 chunk
    const int v_coff = (lane >> 4) * 16;        // d-half byte offset

    const int nkt = 2 * qt + 2;                 // k-tiles (64 keys each)

    auto load_tile = [&](int kt, int st) {
        const int kt0 = kt * 64;
        uint32_t ks = sb + st * FSTAGE;
        uint32_t vs = ks + KS_BYTES;
        const __half* ksrc = kp + ((size_t)(bh * SEQ + kt0)) * DHEAD;
        const __half* vsrc = vp + ((size_t)(bh * SEQ + kt0)) * DHEAD;
#pragma unroll
        for (int i = 0; i < 2; i++) {
            int c = i * 256 + tid;               // 0..511
            int row = c >> 3, ch = c & 7;
            uint32_t dk = ks + row * KPITCH + ch * 16;
            uint32_t dv = vs + row * KPITCH + ch * 16;
            const __half* sk = ksrc + (size_t)row * DHEAD + ch * 8;
            const __half* sv = vsrc + (size_t)row * DHEAD + ch * 8;
            asm volatile("cp.async.cg.shared.global [%0], [%1], 16;\n" :: "r"(dk), "l"(sk) : "memory");
            asm volatile("cp.async.cg.shared.global [%0], [%1], 16;\n" :: "r"(dv), "l"(sv) : "memory");
        }
    };

    // ---- overlapped prologue: Q + K/V tile 0 + K/V tile 1, then one wait
    {
        const __half* qsrc = qp + ((size_t)(bh * SEQ + q0)) * DHEAD;
#pragma unroll
        for (int i = 0; i < 4; i++) {
            int c = i * 256 + tid;               // 0..1023 (16B chunks)
            int row = c >> 3, ch = c & 7;
            uint32_t dst = qb + row * KPITCH + ch * 16;
            const __half* src = qsrc + (size_t)row * DHEAD + ch * 8;
            asm volatile("cp.async.cg.shared.global [%0], [%1], 16;\n" :: "r"(dst), "l"(src) : "memory");
        }
        asm volatile("cp.async.commit_group;\n" ::: "memory");
    }
    load_tile(0, 0);
    asm volatile("cp.async.commit_group;\n" ::: "memory");
    load_tile(1, 1);
    asm volatile("cp.async.commit_group;\n" ::: "memory");

    // Q group done when <=2 groups pending
    asm volatile("cp.async.wait_group 2;\n" ::: "memory");
    __syncthreads();

    uint32_t qf[4][4];
#pragma unroll
    for (int ck = 0; ck < 4; ck++) {
        uint32_t addr = qb + (warp * 16 + a_row_off) * KPITCH + ck * 32 + a_kch * 16;
        LDMATRIX_X4(qf[ck][0], qf[ck][1], qf[ck][2], qf[ck][3], addr);
    }

    float oacc[8][4];
#pragma unroll
    for (int t = 0; t < 8; t++)
#pragma unroll
        for (int r = 0; r < 4; r++) oacc[t][r] = 0.f;
    float m0 = -1e30f, m1 = -1e30f, l0 = 0.f, l1 = 0.f;

    for (int kt = 0; kt < nkt; kt++) {
        asm volatile("cp.async.wait_group 1;\n" ::: "memory");
        __syncthreads();
        const int st = kt & 1;
        uint32_t ks = sb + st * FSTAGE;
        uint32_t vs = ks + KS_BYTES;

        // warps 0-3 on the last k-tile are fully above the diagonal:
        // their P is exactly 0 there, so skip the compute entirely.
        const bool active = !(kt == nkt - 1 && warp < 4);
        if (active) {
            // ---- S = Q.K^T  (4 k16 chunks over DHEAD=64)
            float sacc[8][4];
#pragma unroll
            for (int t = 0; t < 8; t++)
#pragma unroll
                for (int r = 0; r < 4; r++) sacc[t][r] = 0.f;
#pragma unroll
            for (int ck = 0; ck < 4; ck++) {
                uint32_t bfr[4][4];
#pragma unroll
                for (int nj = 0; nj < 4; nj++) {
                    uint32_t addr = ks + (nj * 16 + b_row_off) * KPITCH + ck * 32 + b_kch * 16;
                    LDMATRIX_X4(bfr[nj][0], bfr[nj][1], bfr[nj][2], bfr[nj][3], addr);
                }
#pragma unroll
                for (int ni = 0; ni < 8; ni++)
                    MMA_F16(sacc[ni], qf[ck][0], qf[ck][1], qf[ck][2], qf[ck][3],
                            bfr[ni >> 1][(ni & 1) * 2 + 0], bfr[ni >> 1][(ni & 1) * 2 + 1]);
            }

            // ---- causal mask on the two diagonal-spanning k-tiles
            if (kt >= nkt - 2) {
                const int kt0 = kt * 64;
                int rq0 = q0 + warp * 16 + gr;
                int rq1 = rq0 + 8;
#pragma unroll
                for (int t = 0; t < 8; t++) {
                    int c0 = kt0 + 8 * t + 2 * tc;
                    if (c0 > rq0)     sacc[t][0] = -1e30f;
                    if (c0 + 1 > rq0) sacc[t][1] = -1e30f;
                    if (c0 > rq1)     sacc[t][2] = -1e30f;
                    if (c0 + 1 > rq1) sacc[t][3] = -1e30f;
                }
            }

            // ---- online softmax (base-2, quad reductions)
            float mx0 = -1e30f, mx1 = -1e30f;
#pragma unroll
            for (int t = 0; t < 8; t++) {
                mx0 = fmaxf(mx0, fmaxf(sacc[t][0], sacc[t][1]));
                mx1 = fmaxf(mx1, fmaxf(sacc[t][2], sacc[t][3]));
            }
            mx0 = fmaxf(mx0, __shfl_xor_sync(0xffffffffu, mx0, 1));
            mx0 = fmaxf(mx0, __shfl_xor_sync(0xffffffffu, mx0, 2));
            mx1 = fmaxf(mx1, __shfl_xor_sync(0xffffffffu, mx1, 1));
            mx1 = fmaxf(mx1, __shfl_xor_sync(0xffffffffu, mx1, 2));
            float mn0 = fmaxf(m0, mx0), mn1 = fmaxf(m1, mx1);
            float cr0 = fast_exp2(m0 - mn0), cr1 = fast_exp2(m1 - mn1);
            m0 = mn0; m1 = mn1;
            l0 *= cr0; l1 *= cr1;
#pragma unroll
            for (int t = 0; t < 8; t++) {
                oacc[t][0] *= cr0; oacc[t][1] *= cr0;
                oacc[t][2] *= cr1; oacc[t][3] *= cr1;
            }
            uint32_t phi[8][2];
            float rs0 = 0.f, rs1 = 0.f;
#pragma unroll
            for (int t = 0; t < 8; t++) {
                float p0 = fast_exp2(sacc[t][0] - m0);
                float p1 = fast_exp2(sacc[t][1] - m0);
                float p2 = fast_exp2(sacc[t][2] - m1);
                float p3 = fast_exp2(sacc[t][3] - m1);
                rs0 += p0 + p1; rs1 += p2 + p3;
                phi[t][0] = pack_f16x2(p0, p1);
                phi[t][1] = pack_f16x2(p2, p3);
            }
            rs0 += __shfl_xor_sync(0xffffffffu, rs0, 1);
            rs0 += __shfl_xor_sync(0xffffffffu, rs0, 2);
            rs1 += __shfl_xor_sync(0xffffffffu, rs1, 1);
            rs1 += __shfl_xor_sync(0xffffffffu, rs1, 2);
            l0 += rs0; l1 += rs1;

            // ---- PV: O += P.V  (V row-major; B-frags via ldmatrix.trans)
#pragma unroll
            for (int ck = 0; ck < 4; ck++) {
                uint32_t aph[4] = { phi[2 * ck][0], phi[2 * ck][1],
                                    phi[2 * ck + 1][0], phi[2 * ck + 1][1] };
                uint32_t vfr[4][4];
#pragma unroll
                for (int dt = 0; dt < 4; dt++) {
                    uint32_t addr = vs + (ck * 16 + v_row_off) * KPITCH + dt * 32 + v_coff;
                    LDMATRIX_X4_TRANS(vfr[dt][0], vfr[dt][1], vfr[dt][2], vfr[dt][3], addr);
                }
#pragma unroll
                for (int ni = 0; ni < 8; ni++)
                    MMA_F16(oacc[ni], aph[0], aph[1], aph[2], aph[3],
                            vfr[ni >> 1][(ni & 1) * 2 + 0], vfr[ni >> 1][(ni & 1) * 2 + 1]);
            }
        }

        __syncthreads();
        if (kt + 2 < nkt) load_tile(kt + 2, st);
        asm volatile("cp.async.commit_group;\n" ::: "memory");
    }

    // ---- epilogue: write plain fp16 attention output into aP [M x 1024]
    const float inv0 = 1.f / l0, inv1 = 1.f / l1;
    const int qr0 = q0 + warp * 16 + gr;
    const int qr1 = qr0 + 8;
#pragma unroll
    for (int t = 0; t < 8; t++) {
        int col = h * DHEAD + 8 * t + 2 * tc;
        *(__half2*)(aP + ((size_t)(b * SEQ + qr0)) * DMODEL + col) =
            __half2(__float2half_rn(oacc[t][0] * inv0), __float2half_rn(oacc[t][1] * inv0));
        *(__half2*)(aP + ((size_t)(b * SEQ + qr1)) * DMODEL + col) =
            __half2(__float2half_rn(oacc[t][2] * inv1), __float2half_rn(oacc[t][3] * inv1));
    }
}

// ---------------------------------------------------------------------------
extern "C" void kernel_launch(void* const* d_in, const int* in_sizes, int n_in,
                              void* d_out, int out_size)
{
    const float* x     = (const float*)d_in[0];
    const float* W_qkv = (const float*)d_in[1];
    const float* W_o   = (const float*)d_in[2];
    float* out = (float*)d_out;

    __half *aP, *w1P, *w2P, *qp, *kp, *vp;
    cudaGetSymbolAddress((void**)&aP, g_aP);
    cudaGetSymbolAddress((void**)&w1P, g_w1P);
    cudaGetSymbolAddress((void**)&w2P, g_w2P);
    cudaGetSymbolAddress((void**)&qp, g_qp);
    cudaGetSymbolAddress((void**)&kp, g_kp);
    cudaGetSymbolAddress((void**)&vp, g_vp);

    cudaFuncSetAttribute(flash_mma_kernel,
                         cudaFuncAttributeMaxDynamicSharedMemorySize, FSMEM);
    cudaFuncSetAttribute(mma_gemm_kernel,
                         cudaFuncAttributeMaxDynamicSharedMemorySize, GSMEM2);
    cudaFuncSetAttribute(mma_gemm_qkv_kernel,
                         cudaFuncAttributeMaxDynamicSharedMemorySize, GSMEM1);

    // all conversions in one launch
    conv_all_kernel<<<4096 + 3072 + 1024, 256>>>(x, W_qkv, W_o, aP, w1P, w2P);

    // 1) QKV GEMM with fused Q/K/V fp16 epilogue   (M=4096, N=3072, K=1024)
    {
        dim3 grid(QKV_COLS / 128, MROWS / 128);
        mma_gemm_qkv_kernel<<<grid, 128, GSMEM1>>>(aP, w1P, qp, kp, vp,
                                                   QKV_COLS, DMODEL);
    }
    // 2) flash attention (q-tile 128, writes fp16 aP for out-proj)
    {
        dim3 grid(SEQ / 128, NHEAD, BATCH);
        flash_mma_kernel<<<grid, 256, FSMEM>>>(qp, kp, vp, aP);
    }
    // 3) out = attn_out @ W_o   (M=4096, N=1024, K=1024)
    {
        dim3 grid(DMODEL / 128, MROWS / 128);
        mma_gemm_kernel<<<grid, 128, GSMEM2>>>(aP, w2P, out, DMODEL, DMODEL);
    }
}